// round 5
// baseline (speedup 1.0000x reference)
#include <cuda_runtime.h>
#include <cuda_bf16.h>
#include <cstdint>
#include <math.h>

// Problem constants
#define BB 2
#define SS 2048
#define TT (BB*SS)        // 4096 tokens
#define HH 2048
#define NHQ 16
#define NKV 8
#define HD 128
#define INTER 8192
#define EPS 1e-6f

// ======================= scratch (__device__ globals) =======================
__device__ __align__(256) float g_res1 [(size_t)TT*HH];
__device__ __align__(256) float g_q    [(size_t)TT*NHQ*HD];
__device__ __align__(256) float g_k    [(size_t)TT*NKV*HD];
__device__ __align__(256) float g_v    [(size_t)TT*NKV*HD];
__device__ __align__(256) float g_hattn[(size_t)TT*HH];
__device__ __align__(256) float g_gu   [(size_t)TT*2*INTER];
__device__ float g_invf [64];

// bf16 split activations
__device__ __align__(256) __nv_bfloat16 g_xn_h [(size_t)TT*HH];
__device__ __align__(256) __nv_bfloat16 g_xn_l [(size_t)TT*HH];
__device__ __align__(256) __nv_bfloat16 g_at_h [(size_t)TT*HH];
__device__ __align__(256) __nv_bfloat16 g_at_l [(size_t)TT*HH];
__device__ __align__(256) __nv_bfloat16 g_h2_h [(size_t)TT*HH];
__device__ __align__(256) __nv_bfloat16 g_h2_l [(size_t)TT*HH];
__device__ __align__(256) __nv_bfloat16 g_ac_h [(size_t)TT*INTER];
__device__ __align__(256) __nv_bfloat16 g_ac_l [(size_t)TT*INTER];

// bf16 split transposed weights [N, K]
__device__ __align__(256) __nv_bfloat16 g_wqT_h[(size_t)(NHQ*HD)*HH];
__device__ __align__(256) __nv_bfloat16 g_wqT_l[(size_t)(NHQ*HD)*HH];
__device__ __align__(256) __nv_bfloat16 g_wkT_h[(size_t)(NKV*HD)*HH];
__device__ __align__(256) __nv_bfloat16 g_wkT_l[(size_t)(NKV*HD)*HH];
__device__ __align__(256) __nv_bfloat16 g_wvT_h[(size_t)(NKV*HD)*HH];
__device__ __align__(256) __nv_bfloat16 g_wvT_l[(size_t)(NKV*HD)*HH];
__device__ __align__(256) __nv_bfloat16 g_woT_h[(size_t)HH*(NHQ*HD)];
__device__ __align__(256) __nv_bfloat16 g_woT_l[(size_t)HH*(NHQ*HD)];
__device__ __align__(256) __nv_bfloat16 g_guT_h[(size_t)(2*INTER)*HH];
__device__ __align__(256) __nv_bfloat16 g_guT_l[(size_t)(2*INTER)*HH];
__device__ __align__(256) __nv_bfloat16 g_wdT_h[(size_t)HH*INTER];
__device__ __align__(256) __nv_bfloat16 g_wdT_l[(size_t)HH*INTER];

// ======================= PTX helpers (baseline sm_80/90 features only) =======================
__device__ __forceinline__ uint32_t s2u(const void* p) {
    uint32_t a;
    asm("{ .reg .u64 t; cvta.to.shared.u64 t, %1; cvt.u32.u64 %0, t; }" : "=r"(a) : "l"(p));
    return a;
}
__device__ __forceinline__ void cpasync16(uint32_t dst, const void* src) {
    asm volatile("cp.async.cg.shared.global [%0], [%1], 16;" :: "r"(dst), "l"(src) : "memory");
}
__device__ __forceinline__ void cp_commit() {
    asm volatile("cp.async.commit_group;" ::: "memory");
}
template<int N_>
__device__ __forceinline__ void cp_wait() {
    asm volatile("cp.async.wait_group %0;" :: "n"(N_) : "memory");
}
__device__ __forceinline__ void ldsm4(uint32_t* r, uint32_t addr) {
    asm volatile("ldmatrix.sync.aligned.m8n8.x4.shared.b16 {%0,%1,%2,%3}, [%4];"
                 : "=r"(r[0]), "=r"(r[1]), "=r"(r[2]), "=r"(r[3]) : "r"(addr));
}
__device__ __forceinline__ void mma_bf16(float* d, const uint32_t* a, const uint32_t* b) {
    asm volatile(
        "mma.sync.aligned.m16n8k16.row.col.f32.bf16.bf16.f32 "
        "{%0,%1,%2,%3}, {%4,%5,%6,%7}, {%8,%9}, {%0,%1,%2,%3};"
        : "+f"(d[0]), "+f"(d[1]), "+f"(d[2]), "+f"(d[3])
        : "r"(a[0]), "r"(a[1]), "r"(a[2]), "r"(a[3]), "r"(b[0]), "r"(b[1]));
}

// ======================= bf16 split helpers =======================
__device__ __forceinline__ void split_store2(float x, float y,
                                             __nv_bfloat162* ph, __nv_bfloat162* pl)
{
    __nv_bfloat16 hx = __float2bfloat16(x), hy = __float2bfloat16(y);
    *ph = __halves2bfloat162(hx, hy);
    *pl = __halves2bfloat162(__float2bfloat16(x - __bfloat162float(hx)),
                             __float2bfloat16(y - __bfloat162float(hy)));
}

// ======================= fused add + RMSNorm (bf16-split output) =======================
__global__ void add_rmsnorm_kernel(const float* __restrict__ a, const float* __restrict__ b,
                                   const float* __restrict__ w, float* __restrict__ res,
                                   __nv_bfloat16* __restrict__ oh, __nv_bfloat16* __restrict__ ol)
{
    int t = blockIdx.x, tid = threadIdx.x;
    const float4* a4 = (const float4*)(a + (size_t)t * HH);
    const float4* b4 = (const float4*)(b + (size_t)t * HH);
    float4* r4 = (float4*)(res + (size_t)t * HH);
    const float4* w4 = (const float4*)w;
    __nv_bfloat162* oh2 = (__nv_bfloat162*)(oh + (size_t)t * HH);
    __nv_bfloat162* ol2 = (__nv_bfloat162*)(ol + (size_t)t * HH);

    float4 vv[2];
    float ss = 0.f;
#pragma unroll
    for (int ii = 0; ii < 2; ii++) {
        int idx = tid + ii * 256;
        float4 x = a4[idx], y = b4[idx];
        x.x += y.x; x.y += y.y; x.z += y.z; x.w += y.w;
        r4[idx] = x;
        vv[ii] = x;
        ss += x.x*x.x + x.y*x.y + x.z*x.z + x.w*x.w;
    }
#pragma unroll
    for (int off = 16; off; off >>= 1) ss += __shfl_xor_sync(0xffffffffu, ss, off);
    __shared__ float sh[8];
    __shared__ float s_inv;
    if ((tid & 31) == 0) sh[tid >> 5] = ss;
    __syncthreads();
    if (tid == 0) {
        float s = 0.f;
#pragma unroll
        for (int i = 0; i < 8; i++) s += sh[i];
        s_inv = rsqrtf(s / (float)HH + EPS);
    }
    __syncthreads();
    float inv = s_inv;
#pragma unroll
    for (int ii = 0; ii < 2; ii++) {
        int idx = tid + ii * 256;
        float4 x = vv[ii];
        float4 ww = w4[idx];
        float o0 = x.x*inv*ww.x, o1 = x.y*inv*ww.y, o2 = x.z*inv*ww.z, o3 = x.w*inv*ww.w;
        __nv_bfloat162 h0, l0, h1, l1;
        split_store2(o0, o1, &h0, &l0);
        split_store2(o2, o3, &h1, &l1);
        oh2[idx*2]   = h0; oh2[idx*2+1] = h1;
        ol2[idx*2]   = l0; ol2[idx*2+1] = l1;
    }
}

// ======================= weight transpose + split: W[K,N] -> T_hi/T_lo [N,K] =======================
__global__ void wsplit_kernel(const float* __restrict__ W,
                              __nv_bfloat16* __restrict__ Th, __nv_bfloat16* __restrict__ Tl,
                              int K, int N)
{
    __shared__ float tile[32][33];
    int k0 = blockIdx.y * 32, n0 = blockIdx.x * 32;
    int tx = threadIdx.x, ty = threadIdx.y;
#pragma unroll
    for (int j = 0; j < 4; j++)
        tile[ty + 8*j][tx] = W[(size_t)(k0 + ty + 8*j) * N + n0 + tx];
    __syncthreads();
#pragma unroll
    for (int j = 0; j < 4; j++) {
        int n = ty + 8*j;
        float v = tile[tx][n];
        __nv_bfloat16 h = __float2bfloat16(v);
        float lo = v - __bfloat162float(h);
        Th[(size_t)(n0 + n) * K + k0 + tx] = h;
        Tl[(size_t)(n0 + n) * K + k0 + tx] = __float2bfloat16(lo);
    }
}

// ======================= mma.sync bf16-split GEMM =======================
// C[M,N] = Ah@BhT + Ah@BlT + Al@BhT (+bias). A[M,K] bf16 pair, B[N,K] bf16 pair.
// CTA: 128x128, BK=32 (two k16 steps), 256 threads = 2(M) x 4(N) warps, warp tile 64x32.
#define SO_AH 0
#define SO_AL 8192
#define SO_BH 16384
#define SO_BL 24576
#define STAGE_STRIDE 32768
#define GEMM_SMEM 65536
// swizzled 16B-unit offset within a [128 rows][32 halves] tile
__device__ __forceinline__ uint32_t soff(int row, int u) {
    return (uint32_t)(row * 64 + ((u ^ ((row >> 1) & 3)) << 4));
}

__global__ __launch_bounds__(256, 1) void gemm_mma(
    const __nv_bfloat16* __restrict__ Ah, const __nv_bfloat16* __restrict__ Al,
    const __nv_bfloat16* __restrict__ Bh, const __nv_bfloat16* __restrict__ Bl,
    const float* __restrict__ bias, float* __restrict__ C, int M, int N, int K)
{
    extern __shared__ char smc[];
    uint32_t sb = s2u(smc);
    int tid = threadIdx.x, lane = tid & 31, wid = tid >> 5;
    int wm = wid >> 2, wn = wid & 3;
    int m0 = blockIdx.y * 128, n0 = blockIdx.x * 128;

    float acc[4][4][4];
#pragma unroll
    for (int i = 0; i < 4; i++)
#pragma unroll
        for (int j = 0; j < 4; j++)
#pragma unroll
            for (int c = 0; c < 4; c++) acc[i][j][c] = 0.f;

    // loader: 512 16B-chunks per tile / 256 threads = 2 rows per thread (row, row+64)
    int lrow = tid >> 2, lu = tid & 3;
    uint32_t ls0 = soff(lrow, lu), ls1 = soff(lrow + 64, lu);
    size_t gaoff0 = (size_t)(m0 + lrow) * K + lu * 8;
    size_t gaoff1 = (size_t)(m0 + lrow + 64) * K + lu * 8;
    size_t gboff0 = (size_t)(n0 + lrow) * K + lu * 8;
    size_t gboff1 = (size_t)(n0 + lrow + 64) * K + lu * 8;

    // fragment lane mappings
    int rA = lane & 15, uA = lane >> 4;                 // A ldmatrix.x4
    int rB = (lane & 7) | ((lane & 16) >> 1);           // B ldmatrix.x4
    int uB = (lane >> 3) & 1;

    int nIter = K / 32;

    // prologue: stage 0
    {
        uint32_t s = sb;
        cpasync16(s + SO_AH + ls0, Ah + gaoff0);
        cpasync16(s + SO_AH + ls1, Ah + gaoff1);
        cpasync16(s + SO_AL + ls0, Al + gaoff0);
        cpasync16(s + SO_AL + ls1, Al + gaoff1);
        cpasync16(s + SO_BH + ls0, Bh + gboff0);
        cpasync16(s + SO_BH + ls1, Bh + gboff1);
        cpasync16(s + SO_BL + ls0, Bl + gboff0);
        cpasync16(s + SO_BL + ls1, Bl + gboff1);
        cp_commit();
    }

    for (int it = 0; it < nIter; it++) {
        if (it + 1 < nIter) {
            uint32_t s = sb + ((it + 1) & 1) * STAGE_STRIDE;
            size_t ko = (size_t)(it + 1) * 32;
            cpasync16(s + SO_AH + ls0, Ah + gaoff0 + ko);
            cpasync16(s + SO_AH + ls1, Ah + gaoff1 + ko);
            cpasync16(s + SO_AL + ls0, Al + gaoff0 + ko);
            cpasync16(s + SO_AL + ls1, Al + gaoff1 + ko);
            cpasync16(s + SO_BH + ls0, Bh + gboff0 + ko);
            cpasync16(s + SO_BH + ls1, Bh + gboff1 + ko);
            cpasync16(s + SO_BL + ls0, Bl + gboff0 + ko);
            cpasync16(s + SO_BL + ls1, Bl + gboff1 + ko);
            cp_commit();
            cp_wait<1>();
        } else {
            cp_wait<0>();
        }
        __syncthreads();

        uint32_t s = sb + (it & 1) * STAGE_STRIDE;
#pragma unroll
        for (int ks = 0; ks < 2; ks++) {
            uint32_t ah[4][4], al[4][4], bh[4][2], bl[4][2];
#pragma unroll
            for (int mt = 0; mt < 4; mt++) {
                uint32_t off = soff(wm * 64 + mt * 16 + rA, ks * 2 + uA);
                ldsm4(ah[mt], s + SO_AH + off);
                ldsm4(al[mt], s + SO_AL + off);
            }
#pragma unroll
            for (int nt = 0; nt < 2; nt++) {
                uint32_t off = soff(wn * 32 + nt * 16 + rB, ks * 2 + uB);
                uint32_t t4[4];
                ldsm4(t4, s + SO_BH + off);
                bh[nt*2][0] = t4[0]; bh[nt*2][1] = t4[1];
                bh[nt*2+1][0] = t4[2]; bh[nt*2+1][1] = t4[3];
                ldsm4(t4, s + SO_BL + off);
                bl[nt*2][0] = t4[0]; bl[nt*2][1] = t4[1];
                bl[nt*2+1][0] = t4[2]; bl[nt*2+1][1] = t4[3];
            }
#pragma unroll
            for (int mt = 0; mt < 4; mt++)
#pragma unroll
                for (int nf = 0; nf < 4; nf++) {
                    mma_bf16(acc[mt][nf], ah[mt], bh[nf]);
                    mma_bf16(acc[mt][nf], ah[mt], bl[nf]);
                    mma_bf16(acc[mt][nf], al[mt], bh[nf]);
                }
        }
        __syncthreads();
    }

    // epilogue
    int crow = lane >> 2, ccol = (lane & 3) * 2;
#pragma unroll
    for (int mt = 0; mt < 4; mt++) {
#pragma unroll
        for (int nf = 0; nf < 4; nf++) {
            int r = m0 + wm * 64 + mt * 16 + crow;
            int cidx = n0 + wn * 32 + nf * 8 + ccol;
            float b0 = 0.f, b1 = 0.f;
            if (bias) { b0 = bias[cidx]; b1 = bias[cidx + 1]; }
            float2 v0 = make_float2(acc[mt][nf][0] + b0, acc[mt][nf][1] + b1);
            float2 v1 = make_float2(acc[mt][nf][2] + b0, acc[mt][nf][3] + b1);
            *(float2*)(C + (size_t)r * N + cidx) = v0;
            *(float2*)(C + (size_t)(r + 8) * N + cidx) = v1;
        }
    }
}

// ======================= RoPE =======================
__global__ void init_freq_kernel()
{
    int i = threadIdx.x;
    if (i < 64) g_invf[i] = (float)pow(1.0e6, -(double)i / 64.0);
}

__global__ void rope_kernel(float* __restrict__ q, float* __restrict__ k,
                            const int* __restrict__ pos)
{
    int idx = blockIdx.x * blockDim.x + threadIdx.x;
    int i = idx & 63;
    int rest = idx >> 6;
    int head = rest % (NHQ + NKV);
    int t = rest / (NHQ + NKV);
    if (t >= TT) return;
    float* p;
    if (head < NHQ) p = q + ((size_t)t * NHQ + head) * HD;
    else            p = k + ((size_t)t * NKV + (head - NHQ)) * HD;
    float ang = (float)pos[t] * g_invf[i];
    float sv, cv;
    sincosf(ang, &sv, &cv);
    float x1 = p[i], x2 = p[i + 64];
    p[i]      = x1 * cv - x2 * sv;
    p[i + 64] = x2 * cv + x1 * sv;
}

// ======================= causal flash attention (fp32, GQA rep=2) =======================
#define QT_PITCH 68
#define FLASH_SMEM ((2 * 128 * QT_PITCH + 64 * 128 + 64 * QT_PITCH) * 4)

__global__ __launch_bounds__(256) void flash_kernel(
    const float* __restrict__ q, const float* __restrict__ k,
    const float* __restrict__ v,
    __nv_bfloat16* __restrict__ oh, __nv_bfloat16* __restrict__ ol)
{
    extern __shared__ float smf[];
    float* Qt = smf;
    float* Kt = Qt + 128 * QT_PITCH;
    float* Vs = Kt + 128 * QT_PITCH;
    float* Pt = Vs + 64 * 128;

    int qt = blockIdx.x, h = blockIdx.y, b = blockIdx.z;
    int tid = threadIdx.x, tx = tid & 15, ty = tid >> 4;
    int qbase = qt * 64;
    int hk = h >> 1;

    for (int i = tid; i < 64 * 32; i += 256) {
        int r = i >> 5, c4 = (i & 31) * 4;
        float4 val = *(const float4*)(q + (((size_t)(b * SS + qbase + r) * NHQ + h) * HD + c4));
        Qt[(c4 + 0) * QT_PITCH + r] = val.x;
        Qt[(c4 + 1) * QT_PITCH + r] = val.y;
        Qt[(c4 + 2) * QT_PITCH + r] = val.z;
        Qt[(c4 + 3) * QT_PITCH + r] = val.w;
    }

    float m[4], l[4], accO[4][8];
#pragma unroll
    for (int i = 0; i < 4; i++) {
        m[i] = -1e30f; l[i] = 0.f;
#pragma unroll
        for (int c = 0; c < 8; c++) accO[i][c] = 0.f;
    }

    const float scale = 0.08838834764831845f;

    for (int kt = 0; kt <= qt; kt++) {
        int kbase = kt * 64;
        __syncthreads();
        for (int i = tid; i < 64 * 32; i += 256) {
            int r = i >> 5, c4 = (i & 31) * 4;
            size_t base = ((size_t)(b * SS + kbase + r) * NKV + hk) * HD + c4;
            float4 kv = *(const float4*)(k + base);
            Kt[(c4 + 0) * QT_PITCH + r] = kv.x;
            Kt[(c4 + 1) * QT_PITCH + r] = kv.y;
            Kt[(c4 + 2) * QT_PITCH + r] = kv.z;
            Kt[(c4 + 3) * QT_PITCH + r] = kv.w;
            float4 vv = *(const float4*)(v + base);
            *(float4*)&Vs[r * 128 + c4] = vv;
        }
        __syncthreads();

        float accS[4][4];
#pragma unroll
        for (int i = 0; i < 4; i++)
#pragma unroll
            for (int j = 0; j < 4; j++) accS[i][j] = 0.f;
#pragma unroll 8
        for (int d = 0; d < 128; d++) {
            float4 a = *(const float4*)&Qt[d * QT_PITCH + ty * 4];
            float4 bb = *(const float4*)&Kt[d * QT_PITCH + tx * 4];
            float av[4] = {a.x, a.y, a.z, a.w};
            float bv[4] = {bb.x, bb.y, bb.z, bb.w};
#pragma unroll
            for (int i = 0; i < 4; i++)
#pragma unroll
                for (int j = 0; j < 4; j++) accS[i][j] += av[i] * bv[j];
        }

        bool diag = (kt == qt);
#pragma unroll
        for (int i = 0; i < 4; i++) {
#pragma unroll
            for (int j = 0; j < 4; j++) {
                float s = accS[i][j] * scale;
                if (diag && (tx * 4 + j > ty * 4 + i)) s = -1e30f;
                accS[i][j] = s;
            }
            float rm = fmaxf(fmaxf(accS[i][0], accS[i][1]), fmaxf(accS[i][2], accS[i][3]));
#pragma unroll
            for (int off = 8; off; off >>= 1) rm = fmaxf(rm, __shfl_xor_sync(0xffffffffu, rm, off));
            float mn = fmaxf(m[i], rm);
            float corr = __expf(m[i] - mn);
            float p[4], rs = 0.f;
#pragma unroll
            for (int j = 0; j < 4; j++) { p[j] = __expf(accS[i][j] - mn); rs += p[j]; }
#pragma unroll
            for (int off = 8; off; off >>= 1) rs += __shfl_xor_sync(0xffffffffu, rs, off);
            l[i] = l[i] * corr + rs;
            m[i] = mn;
#pragma unroll
            for (int c = 0; c < 8; c++) accO[i][c] *= corr;
#pragma unroll
            for (int j = 0; j < 4; j++) Pt[(tx * 4 + j) * QT_PITCH + ty * 4 + i] = p[j];
        }
        __syncthreads();

#pragma unroll 4
        for (int j = 0; j < 64; j++) {
            float4 p4 = *(const float4*)&Pt[j * QT_PITCH + ty * 4];
            float4 v0 = *(const float4*)&Vs[j * 128 + tx * 8];
            float4 v1 = *(const float4*)&Vs[j * 128 + tx * 8 + 4];
            float pp[4] = {p4.x, p4.y, p4.z, p4.w};
            float vv[8] = {v0.x, v0.y, v0.z, v0.w, v1.x, v1.y, v1.z, v1.w};
#pragma unroll
            for (int i = 0; i < 4; i++)
#pragma unroll
                for (int c = 0; c < 8; c++) accO[i][c] += pp[i] * vv[c];
        }
    }

#pragma unroll
    for (int i = 0; i < 4; i++) {
        float invl = 1.0f / l[i];
        int row = qbase + ty * 4 + i;
        size_t off = ((size_t)(b * SS + row) * NHQ + h) * HD + tx * 8;
        __nv_bfloat162* oph = (__nv_bfloat162*)(oh + off);
        __nv_bfloat162* opl = (__nv_bfloat162*)(ol + off);
#pragma unroll
        for (int c = 0; c < 8; c += 2) {
            __nv_bfloat162 hh, ll;
            split_store2(accO[i][c] * invl, accO[i][c+1] * invl, &hh, &ll);
            oph[c >> 1] = hh;
            opl[c >> 1] = ll;
        }
    }
}

// ======================= SiLU * up (bf16-split output) =======================
__global__ void silu_mul_kernel(const float* __restrict__ gu,
                                __nv_bfloat16* __restrict__ ah, __nv_bfloat16* __restrict__ al)
{
    size_t idx = (size_t)blockIdx.x * blockDim.x + threadIdx.x;  // over TT*(INTER/4)
    size_t t = idx >> 11;
    size_t c = idx & 2047;
    const float4 g = *(const float4*)(gu + t * (2 * INTER) + c * 4);
    const float4 u = *(const float4*)(gu + t * (2 * INTER) + INTER + c * 4);
    float r0 = g.x / (1.f + __expf(-g.x)) * u.x;
    float r1 = g.y / (1.f + __expf(-g.y)) * u.y;
    float r2 = g.z / (1.f + __expf(-g.z)) * u.z;
    float r3 = g.w / (1.f + __expf(-g.w)) * u.w;
    __nv_bfloat162 h0, l0, h1, l1;
    split_store2(r0, r1, &h0, &l0);
    split_store2(r2, r3, &h1, &l1);
    __nv_bfloat162* ph = (__nv_bfloat162*)(ah + t * INTER + c * 4);
    __nv_bfloat162* pl = (__nv_bfloat162*)(al + t * INTER + c * 4);
    ph[0] = h0; ph[1] = h1;
    pl[0] = l0; pl[1] = l1;
}

// ======================= launch =======================
extern "C" void kernel_launch(void* const* d_in, const int* in_sizes, int n_in,
                              void* d_out, int out_size)
{
    const int*   positions = (const int*)  d_in[0];
    const float* hidden    = (const float*)d_in[1];
    const float* residual  = (const float*)d_in[2];
    const float* ln1       = (const float*)d_in[3];
    const float* ln2       = (const float*)d_in[4];
    const float* wq        = (const float*)d_in[5];
    const float* bq        = (const float*)d_in[6];
    const float* wk        = (const float*)d_in[7];
    const float* bk        = (const float*)d_in[8];
    const float* wv        = (const float*)d_in[9];
    const float* bv        = (const float*)d_in[10];
    const float* wo        = (const float*)d_in[11];
    const float* wgu       = (const float*)d_in[12];
    const float* wd        = (const float*)d_in[13];

    float* out_h   = (float*)d_out;
    float* out_res = out_h + (size_t)out_size / 2;

    float *res1, *q, *k, *v, *hattn, *gu;
    __nv_bfloat16 *xn_h, *xn_l, *at_h, *at_l, *h2_h, *h2_l, *ac_h, *ac_l;
    __nv_bfloat16 *wqT_h, *wqT_l, *wkT_h, *wkT_l, *wvT_h, *wvT_l;
    __nv_bfloat16 *woT_h, *woT_l, *guT_h, *guT_l, *wdT_h, *wdT_l;
    cudaGetSymbolAddress((void**)&res1,  g_res1);
    cudaGetSymbolAddress((void**)&q,     g_q);
    cudaGetSymbolAddress((void**)&k,     g_k);
    cudaGetSymbolAddress((void**)&v,     g_v);
    cudaGetSymbolAddress((void**)&hattn, g_hattn);
    cudaGetSymbolAddress((void**)&gu,    g_gu);
    cudaGetSymbolAddress((void**)&xn_h,  g_xn_h);
    cudaGetSymbolAddress((void**)&xn_l,  g_xn_l);
    cudaGetSymbolAddress((void**)&at_h,  g_at_h);
    cudaGetSymbolAddress((void**)&at_l,  g_at_l);
    cudaGetSymbolAddress((void**)&h2_h,  g_h2_h);
    cudaGetSymbolAddress((void**)&h2_l,  g_h2_l);
    cudaGetSymbolAddress((void**)&ac_h,  g_ac_h);
    cudaGetSymbolAddress((void**)&ac_l,  g_ac_l);
    cudaGetSymbolAddress((void**)&wqT_h, g_wqT_h);
    cudaGetSymbolAddress((void**)&wqT_l, g_wqT_l);
    cudaGetSymbolAddress((void**)&wkT_h, g_wkT_h);
    cudaGetSymbolAddress((void**)&wkT_l, g_wkT_l);
    cudaGetSymbolAddress((void**)&wvT_h, g_wvT_h);
    cudaGetSymbolAddress((void**)&wvT_l, g_wvT_l);
    cudaGetSymbolAddress((void**)&woT_h, g_woT_h);
    cudaGetSymbolAddress((void**)&woT_l, g_woT_l);
    cudaGetSymbolAddress((void**)&guT_h, g_guT_h);
    cudaGetSymbolAddress((void**)&guT_l, g_guT_l);
    cudaGetSymbolAddress((void**)&wdT_h, g_wdT_h);
    cudaGetSymbolAddress((void**)&wdT_l, g_wdT_l);

    cudaFuncSetAttribute(gemm_mma, cudaFuncAttributeMaxDynamicSharedMemorySize, GEMM_SMEM);
    cudaFuncSetAttribute(flash_kernel, cudaFuncAttributeMaxDynamicSharedMemorySize, FLASH_SMEM);

    // 0. weight transpose + bf16 split
    wsplit_kernel<<<dim3((NHQ*HD)/32, HH/32), dim3(32,8)>>>(wq, wqT_h, wqT_l, HH, NHQ*HD);
    wsplit_kernel<<<dim3((NKV*HD)/32, HH/32), dim3(32,8)>>>(wk, wkT_h, wkT_l, HH, NKV*HD);
    wsplit_kernel<<<dim3((NKV*HD)/32, HH/32), dim3(32,8)>>>(wv, wvT_h, wvT_l, HH, NKV*HD);
    wsplit_kernel<<<dim3(HH/32, (NHQ*HD)/32), dim3(32,8)>>>(wo, woT_h, woT_l, NHQ*HD, HH);
    wsplit_kernel<<<dim3((2*INTER)/32, HH/32), dim3(32,8)>>>(wgu, guT_h, guT_l, HH, 2*INTER);
    wsplit_kernel<<<dim3(HH/32, INTER/32), dim3(32,8)>>>(wd, wdT_h, wdT_l, INTER, HH);

    // 1. res1 = hidden + residual ; xn = rmsnorm(res1)*ln1 (bf16 split)
    add_rmsnorm_kernel<<<TT, 256>>>(hidden, residual, ln1, res1, xn_h, xn_l);

    // 2. QKV projections (tensor cores via mma.sync)
    gemm_mma<<<dim3((NHQ*HD)/128, TT/128), 256, GEMM_SMEM>>>(xn_h, xn_l, wqT_h, wqT_l, bq, q, TT, NHQ*HD, HH);
    gemm_mma<<<dim3((NKV*HD)/128, TT/128), 256, GEMM_SMEM>>>(xn_h, xn_l, wkT_h, wkT_l, bk, k, TT, NKV*HD, HH);
    gemm_mma<<<dim3((NKV*HD)/128, TT/128), 256, GEMM_SMEM>>>(xn_h, xn_l, wvT_h, wvT_l, bv, v, TT, NKV*HD, HH);

    // 3. RoPE
    init_freq_kernel<<<1, 64>>>();
    {
        int total = TT * (NHQ + NKV) * 64;
        rope_kernel<<<(total + 255) / 256, 256>>>(q, k, positions);
    }

    // 4. causal flash attention -> bf16 split
    flash_kernel<<<dim3(SS / 64, NHQ, BB), 256, FLASH_SMEM>>>(q, k, v, at_h, at_l);

    // 5. output projection
    gemm_mma<<<dim3(HH/128, TT/128), 256, GEMM_SMEM>>>(at_h, at_l, woT_h, woT_l, nullptr, hattn, TT, HH, NHQ*HD);

    // 6. res2 = hattn + res1 (-> out second half) ; h2 = rmsnorm(res2)*ln2 (bf16 split)
    add_rmsnorm_kernel<<<TT, 256>>>(hattn, res1, ln2, out_res, h2_h, h2_l);

    // 7. gate_up GEMM
    gemm_mma<<<dim3((2*INTER)/128, TT/128), 256, GEMM_SMEM>>>(h2_h, h2_l, guT_h, guT_l, nullptr, gu, TT, 2*INTER, HH);

    // 8. SiLU * up -> bf16 split
    {
        size_t total4 = (size_t)TT * (INTER / 4);
        silu_mul_kernel<<<(unsigned)(total4 / 256), 256>>>(gu, ac_h, ac_l);
    }

    // 9. down GEMM -> out first half
    gemm_mma<<<dim3(HH/128, TT/128), 256, GEMM_SMEM>>>(ac_h, ac_l, wdT_h, wdT_l, nullptr, out_h, TT, HH, INTER);
}

// round 6
// speedup vs baseline: 1.5455x; 1.5455x over previous
#include <cuda_runtime.h>
#include <cuda_bf16.h>
#include <cstdint>
#include <math.h>

#define BB 2
#define SS 2048
#define TT (BB*SS)
#define HH 2048
#define NHQ 16
#define NKV 8
#define HD 128
#define INTER 8192
#define EPS 1e-6f

// ======================= scratch =======================
__device__ __align__(256) float g_res1 [(size_t)TT*HH];
__device__ __align__(256) float g_qkv  [(size_t)TT*4096];
__device__ __align__(256) float g_hattn[(size_t)TT*HH];
__device__ float g_invf [64];

__device__ __align__(256) __nv_bfloat16 g_xn_h [(size_t)TT*HH];
__device__ __align__(256) __nv_bfloat16 g_xn_l [(size_t)TT*HH];
__device__ __align__(256) __nv_bfloat16 g_at_h [(size_t)TT*HH];
__device__ __align__(256) __nv_bfloat16 g_at_l [(size_t)TT*HH];
__device__ __align__(256) __nv_bfloat16 g_h2_h [(size_t)TT*HH];
__device__ __align__(256) __nv_bfloat16 g_h2_l [(size_t)TT*HH];
__device__ __align__(256) __nv_bfloat16 g_ac_h [(size_t)TT*INTER];
__device__ __align__(256) __nv_bfloat16 g_ac_l [(size_t)TT*INTER];

__device__ __align__(256) __nv_bfloat16 g_qkvT_h[(size_t)4096*HH];
__device__ __align__(256) __nv_bfloat16 g_qkvT_l[(size_t)4096*HH];
__device__ __align__(256) __nv_bfloat16 g_woT_h[(size_t)HH*(NHQ*HD)];
__device__ __align__(256) __nv_bfloat16 g_woT_l[(size_t)HH*(NHQ*HD)];
__device__ __align__(256) __nv_bfloat16 g_guT_h[(size_t)(2*INTER)*HH]; // interleaved gate/up
__device__ __align__(256) __nv_bfloat16 g_guT_l[(size_t)(2*INTER)*HH];
__device__ __align__(256) __nv_bfloat16 g_wdT_h[(size_t)HH*INTER];
__device__ __align__(256) __nv_bfloat16 g_wdT_l[(size_t)HH*INTER];

// ======================= PTX helpers =======================
__device__ __forceinline__ uint32_t s2u(const void* p) {
    uint32_t a;
    asm("{ .reg .u64 t; cvta.to.shared.u64 t, %1; cvt.u32.u64 %0, t; }" : "=r"(a) : "l"(p));
    return a;
}
__device__ __forceinline__ void cpasync16(uint32_t dst, const void* src) {
    asm volatile("cp.async.cg.shared.global [%0], [%1], 16;" :: "r"(dst), "l"(src) : "memory");
}
__device__ __forceinline__ void cp_commit() { asm volatile("cp.async.commit_group;" ::: "memory"); }
template<int N_>
__device__ __forceinline__ void cp_wait() { asm volatile("cp.async.wait_group %0;" :: "n"(N_) : "memory"); }
__device__ __forceinline__ void ldsm4(uint32_t* r, uint32_t addr) {
    asm volatile("ldmatrix.sync.aligned.m8n8.x4.shared.b16 {%0,%1,%2,%3}, [%4];"
                 : "=r"(r[0]), "=r"(r[1]), "=r"(r[2]), "=r"(r[3]) : "r"(addr));
}
__device__ __forceinline__ void mma_bf16(float* d, const uint32_t* a, const uint32_t* b) {
    asm volatile(
        "mma.sync.aligned.m16n8k16.row.col.f32.bf16.bf16.f32 "
        "{%0,%1,%2,%3}, {%4,%5,%6,%7}, {%8,%9}, {%0,%1,%2,%3};"
        : "+f"(d[0]), "+f"(d[1]), "+f"(d[2]), "+f"(d[3])
        : "r"(a[0]), "r"(a[1]), "r"(a[2]), "r"(a[3]), "r"(b[0]), "r"(b[1]));
}
__device__ __forceinline__ void split_store2(float x, float y, __nv_bfloat162* ph, __nv_bfloat162* pl)
{
    __nv_bfloat16 hx = __float2bfloat16(x), hy = __float2bfloat16(y);
    *ph = __halves2bfloat162(hx, hy);
    *pl = __halves2bfloat162(__float2bfloat16(x - __bfloat162float(hx)),
                             __float2bfloat16(y - __bfloat162float(hy)));
}
// 128B-row full swizzle, u in 0..7
__device__ __forceinline__ uint32_t soffG(int r, int u) {
    return (uint32_t)(r * 128 + ((u ^ (r & 7)) << 4));
}

// ======================= fused add + RMSNorm =======================
__global__ void add_rmsnorm_kernel(const float* __restrict__ a, const float* __restrict__ b,
                                   const float* __restrict__ w, float* __restrict__ res,
                                   __nv_bfloat16* __restrict__ oh, __nv_bfloat16* __restrict__ ol)
{
    int t = blockIdx.x, tid = threadIdx.x;
    const float4* a4 = (const float4*)(a + (size_t)t * HH);
    const float4* b4 = (const float4*)(b + (size_t)t * HH);
    float4* r4 = (float4*)(res + (size_t)t * HH);
    const float4* w4 = (const float4*)w;
    __nv_bfloat162* oh2 = (__nv_bfloat162*)(oh + (size_t)t * HH);
    __nv_bfloat162* ol2 = (__nv_bfloat162*)(ol + (size_t)t * HH);

    float4 vv[2];
    float ss = 0.f;
#pragma unroll
    for (int ii = 0; ii < 2; ii++) {
        int idx = tid + ii * 256;
        float4 x = a4[idx], y = b4[idx];
        x.x += y.x; x.y += y.y; x.z += y.z; x.w += y.w;
        r4[idx] = x; vv[ii] = x;
        ss += x.x*x.x + x.y*x.y + x.z*x.z + x.w*x.w;
    }
#pragma unroll
    for (int off = 16; off; off >>= 1) ss += __shfl_xor_sync(0xffffffffu, ss, off);
    __shared__ float sh[8];
    __shared__ float s_inv;
    if ((tid & 31) == 0) sh[tid >> 5] = ss;
    __syncthreads();
    if (tid == 0) {
        float s = 0.f;
#pragma unroll
        for (int i = 0; i < 8; i++) s += sh[i];
        s_inv = rsqrtf(s / (float)HH + EPS);
    }
    __syncthreads();
    float inv = s_inv;
#pragma unroll
    for (int ii = 0; ii < 2; ii++) {
        int idx = tid + ii * 256;
        float4 x = vv[ii], ww = w4[idx];
        __nv_bfloat162 h0, l0, h1, l1;
        split_store2(x.x*inv*ww.x, x.y*inv*ww.y, &h0, &l0);
        split_store2(x.z*inv*ww.z, x.w*inv*ww.w, &h1, &l1);
        oh2[idx*2] = h0; oh2[idx*2+1] = h1;
        ol2[idx*2] = l0; ol2[idx*2+1] = l1;
    }
}

// ======================= weight split kernels =======================
__global__ void wsplit_kernel(const float* __restrict__ W,
                              __nv_bfloat16* __restrict__ Th, __nv_bfloat16* __restrict__ Tl,
                              int K, int N)
{
    __shared__ float tile[32][33];
    int k0 = blockIdx.y * 32, n0 = blockIdx.x * 32;
    int tx = threadIdx.x, ty = threadIdx.y;
#pragma unroll
    for (int j = 0; j < 4; j++)
        tile[ty + 8*j][tx] = W[(size_t)(k0 + ty + 8*j) * N + n0 + tx];
    __syncthreads();
#pragma unroll
    for (int j = 0; j < 4; j++) {
        int n = ty + 8*j;
        float v = tile[tx][n];
        __nv_bfloat16 h = __float2bfloat16(v);
        Th[(size_t)(n0 + n) * K + k0 + tx] = h;
        Tl[(size_t)(n0 + n) * K + k0 + tx] = __float2bfloat16(v - __bfloat162float(h));
    }
}

// fused qkv: virtual cols [wq(2048) | wk(1024) | wv(1024)]; also fills g_invf
__global__ void wsplit_qkv_kernel(const float* __restrict__ wq, const float* __restrict__ wk,
                                  const float* __restrict__ wv,
                                  __nv_bfloat16* __restrict__ Th, __nv_bfloat16* __restrict__ Tl)
{
    __shared__ float tile[32][33];
    int n0 = blockIdx.x * 32, k0 = blockIdx.y * 32;
    int tx = threadIdx.x, ty = threadIdx.y;
    if (blockIdx.x == 0 && blockIdx.y == 0) {
        int id = ty * 32 + tx;
        if (id < 64) g_invf[id] = (float)pow(1.0e6, -(double)id / 64.0);
    }
    int n = n0 + tx;
    const float* src; int nc, stride;
    if (n < 2048)      { src = wq; nc = n;        stride = 2048; }
    else if (n < 3072) { src = wk; nc = n - 2048; stride = 1024; }
    else               { src = wv; nc = n - 3072; stride = 1024; }
#pragma unroll
    for (int j = 0; j < 4; j++)
        tile[ty + 8*j][tx] = src[(size_t)(k0 + ty + 8*j) * stride + nc];
    __syncthreads();
#pragma unroll
    for (int j = 0; j < 4; j++) {
        int nn = n0 + ty + 8*j;
        float v = tile[tx][ty + 8*j];
        __nv_bfloat16 h = __float2bfloat16(v);
        Th[(size_t)nn * HH + k0 + tx] = h;
        Tl[(size_t)nn * HH + k0 + tx] = __float2bfloat16(v - __bfloat162float(h));
    }
}

// gate_up interleave: dest row n' <- src col (n'&1 ? 8192+(n'>>1) : n'>>1)
__global__ void wsplit_gu_kernel(const float* __restrict__ W,
                                 __nv_bfloat16* __restrict__ Th, __nv_bfloat16* __restrict__ Tl)
{
    __shared__ float tile[32][33];
    int n0 = blockIdx.x * 32, k0 = blockIdx.y * 32;
    int tx = threadIdx.x, ty = threadIdx.y;
    int n = n0 + tx;
    int srccol = (n & 1) ? (8192 + (n >> 1)) : (n >> 1);
#pragma unroll
    for (int j = 0; j < 4; j++)
        tile[ty + 8*j][tx] = W[(size_t)(k0 + ty + 8*j) * 16384 + srccol];
    __syncthreads();
#pragma unroll
    for (int j = 0; j < 4; j++) {
        int nn = n0 + ty + 8*j;
        float v = tile[tx][ty + 8*j];
        __nv_bfloat16 h = __float2bfloat16(v);
        Th[(size_t)nn * HH + k0 + tx] = h;
        Tl[(size_t)nn * HH + k0 + tx] = __float2bfloat16(v - __bfloat162float(h));
    }
}

// ======================= mma.sync bf16-split GEMM v2 =======================
// packed 128B rows: [hi u0-3 | lo u4-7]; A tile 16KB, B tile 16KB, 3 stages.
#define GS_STAGE 32768
#define GS_B     16384
#define GEMM_SMEM (3*GS_STAGE)

__device__ __forceinline__ void g_load_stage(uint32_t sb, int s,
    const __nv_bfloat16* __restrict__ Ah, const __nv_bfloat16* __restrict__ Al,
    const __nv_bfloat16* __restrict__ Bh, const __nv_bfloat16* __restrict__ Bl,
    int m0, int n0, int k0, int K, int tid)
{
    uint32_t st = sb + s * GS_STAGE;
#pragma unroll
    for (int j = 0; j < 8; j++) {
        int idx = j * 256 + tid;
        int mat = idx >> 10;
        int rem = idx & 1023;
        int r = rem >> 3, u = rem & 7;
        const __nv_bfloat16* src;
        int row = (mat == 0) ? (m0 + r) : (n0 + r);
        if (mat == 0) src = (u < 4) ? Ah : Al;
        else          src = (u < 4) ? Bh : Bl;
        src += (size_t)row * K + k0 + (u & 3) * 8;
        cpasync16(st + mat * GS_B + soffG(r, u), src);
    }
    cp_commit();
}

// MODE 0: f32 out. MODE 1: qkv bias. MODE 2: fused SwiGLU -> bf16 split (cols interleaved).
template<int MODE>
__global__ __launch_bounds__(256, 1) void gemm_mma(
    const __nv_bfloat16* __restrict__ Ah, const __nv_bfloat16* __restrict__ Al,
    const __nv_bfloat16* __restrict__ Bh, const __nv_bfloat16* __restrict__ Bl,
    const float* __restrict__ bq, const float* __restrict__ bk, const float* __restrict__ bv,
    float* __restrict__ C, __nv_bfloat16* __restrict__ actH, __nv_bfloat16* __restrict__ actL,
    int M, int N, int K)
{
    extern __shared__ char smc[];
    uint32_t sb = s2u(smc);
    int tid = threadIdx.x, lane = tid & 31, wid = tid >> 5;
    int wm = wid >> 2, wn = wid & 3;
    int m0 = blockIdx.y * 128, n0 = blockIdx.x * 128;

    float acc[4][4][4];
#pragma unroll
    for (int i = 0; i < 4; i++)
#pragma unroll
        for (int j = 0; j < 4; j++)
#pragma unroll
            for (int c = 0; c < 4; c++) acc[i][j][c] = 0.f;

    int rA = lane & 15, uA = lane >> 4;
    int rB = (lane & 7) | ((lane & 16) >> 1), uB = (lane >> 3) & 1;

    int nIter = K / 32;
    g_load_stage(sb, 0, Ah, Al, Bh, Bl, m0, n0, 0, K, tid);
    g_load_stage(sb, 1, Ah, Al, Bh, Bl, m0, n0, 32, K, tid);

    int cs = 0, ns = 2;
    for (int it = 0; it < nIter; it++) {
        if (it + 1 < nIter) cp_wait<1>(); else cp_wait<0>();
        __syncthreads();
        if (it + 2 < nIter)
            g_load_stage(sb, ns, Ah, Al, Bh, Bl, m0, n0, (it + 2) * 32, K, tid);

        uint32_t st = sb + cs * GS_STAGE;
#pragma unroll
        for (int ks = 0; ks < 2; ks++) {
            uint32_t ah[4][4], al[4][4], bh[4][2], bl[4][2];
#pragma unroll
            for (int mt = 0; mt < 4; mt++) {
                int row = wm * 64 + mt * 16 + rA;
                ldsm4(ah[mt], st + soffG(row, ks * 2 + uA));
                ldsm4(al[mt], st + soffG(row, 4 + ks * 2 + uA));
            }
#pragma unroll
            for (int nt = 0; nt < 2; nt++) {
                int row = wn * 32 + nt * 16 + rB;
                uint32_t t4[4];
                ldsm4(t4, st + GS_B + soffG(row, ks * 2 + uB));
                bh[nt*2][0] = t4[0]; bh[nt*2][1] = t4[1];
                bh[nt*2+1][0] = t4[2]; bh[nt*2+1][1] = t4[3];
                ldsm4(t4, st + GS_B + soffG(row, 4 + ks * 2 + uB));
                bl[nt*2][0] = t4[0]; bl[nt*2][1] = t4[1];
                bl[nt*2+1][0] = t4[2]; bl[nt*2+1][1] = t4[3];
            }
#pragma unroll
            for (int mt = 0; mt < 4; mt++)
#pragma unroll
                for (int nf = 0; nf < 4; nf++) {
                    mma_bf16(acc[mt][nf], ah[mt], bh[nf]);
                    mma_bf16(acc[mt][nf], ah[mt], bl[nf]);
                    mma_bf16(acc[mt][nf], al[mt], bh[nf]);
                }
        }
        cs++; if (cs == 3) cs = 0;
        ns++; if (ns == 3) ns = 0;
    }

    int crow = lane >> 2, ccol = (lane & 3) * 2;
#pragma unroll
    for (int mt = 0; mt < 4; mt++) {
#pragma unroll
        for (int nf = 0; nf < 4; nf++) {
            int r = m0 + wm * 64 + mt * 16 + crow;
            int cidx = n0 + wn * 32 + nf * 8 + ccol;
            if (MODE == 2) {
                int jj = cidx >> 1;
                float ga = acc[mt][nf][0], up = acc[mt][nf][1];
                float v0 = ga / (1.f + __expf(-ga)) * up;
                float gb = acc[mt][nf][2], ub = acc[mt][nf][3];
                float v1 = gb / (1.f + __expf(-gb)) * ub;
                __nv_bfloat16 h0 = __float2bfloat16(v0);
                actH[(size_t)r * INTER + jj] = h0;
                actL[(size_t)r * INTER + jj] = __float2bfloat16(v0 - __bfloat162float(h0));
                __nv_bfloat16 h1 = __float2bfloat16(v1);
                actH[(size_t)(r + 8) * INTER + jj] = h1;
                actL[(size_t)(r + 8) * INTER + jj] = __float2bfloat16(v1 - __bfloat162float(h1));
            } else {
                float b0 = 0.f, b1 = 0.f;
                if (MODE == 1) {
                    b0 = (cidx < 2048) ? bq[cidx] : ((cidx < 3072) ? bk[cidx - 2048] : bv[cidx - 3072]);
                    int c1 = cidx + 1;
                    b1 = (c1 < 2048) ? bq[c1] : ((c1 < 3072) ? bk[c1 - 2048] : bv[c1 - 3072]);
                }
                *(float2*)(C + (size_t)r * N + cidx) =
                    make_float2(acc[mt][nf][0] + b0, acc[mt][nf][1] + b1);
                *(float2*)(C + (size_t)(r + 8) * N + cidx) =
                    make_float2(acc[mt][nf][2] + b0, acc[mt][nf][3] + b1);
            }
        }
    }
}

// ======================= RoPE (in-place on packed qkv) =======================
__global__ void rope_kernel(float* __restrict__ qkv, const int* __restrict__ pos)
{
    int idx = blockIdx.x * blockDim.x + threadIdx.x;
    int i = idx & 63;
    int rest = idx >> 6;
    int head = rest % 24;              // 16 q heads + 8 k heads
    int t = rest / 24;
    if (t >= TT) return;
    float* p = qkv + (size_t)t * 4096 + ((head < 16) ? head * 128 : 2048 + (head - 16) * 128);
    float ang = (float)pos[t] * g_invf[i];
    float sv, cv;
    sincosf(ang, &sv, &cv);
    float x1 = p[i], x2 = p[i + 64];
    p[i]      = x1 * cv - x2 * sv;
    p[i + 64] = x2 * cv + x1 * sv;
}

// ======================= causal flash attention (fp32, reads packed qkv) =======================
#define QT_PITCH 68
#define FLASH_SMEM ((2 * 128 * QT_PITCH + 64 * 128 + 64 * QT_PITCH) * 4)

__global__ __launch_bounds__(256) void flash_kernel(
    const float* __restrict__ qkv,
    __nv_bfloat16* __restrict__ oh, __nv_bfloat16* __restrict__ ol)
{
    extern __shared__ float smf[];
    float* Qt = smf;
    float* Kt = Qt + 128 * QT_PITCH;
    float* Vs = Kt + 128 * QT_PITCH;
    float* Pt = Vs + 64 * 128;

    int qt = blockIdx.x, h = blockIdx.y, b = blockIdx.z;
    int tid = threadIdx.x, tx = tid & 15, ty = tid >> 4;
    int qbase = qt * 64;
    int hk = h >> 1;

    for (int i = tid; i < 64 * 32; i += 256) {
        int r = i >> 5, c4 = (i & 31) * 4;
        float4 val = *(const float4*)(qkv + ((size_t)(b * SS + qbase + r) * 4096 + h * 128 + c4));
        Qt[(c4 + 0) * QT_PITCH + r] = val.x;
        Qt[(c4 + 1) * QT_PITCH + r] = val.y;
        Qt[(c4 + 2) * QT_PITCH + r] = val.z;
        Qt[(c4 + 3) * QT_PITCH + r] = val.w;
    }

    float m[4], l[4], accO[4][8];
#pragma unroll
    for (int i = 0; i < 4; i++) {
        m[i] = -1e30f; l[i] = 0.f;
#pragma unroll
        for (int c = 0; c < 8; c++) accO[i][c] = 0.f;
    }
    const float scale = 0.08838834764831845f;

    for (int kt = 0; kt <= qt; kt++) {
        int kbase = kt * 64;
        __syncthreads();
        for (int i = tid; i < 64 * 32; i += 256) {
            int r = i >> 5, c4 = (i & 31) * 4;
            size_t base = (size_t)(b * SS + kbase + r) * 4096 + hk * 128 + c4;
            float4 kv = *(const float4*)(qkv + 2048 + base);
            Kt[(c4 + 0) * QT_PITCH + r] = kv.x;
            Kt[(c4 + 1) * QT_PITCH + r] = kv.y;
            Kt[(c4 + 2) * QT_PITCH + r] = kv.z;
            Kt[(c4 + 3) * QT_PITCH + r] = kv.w;
            float4 vv = *(const float4*)(qkv + 3072 + base);
            *(float4*)&Vs[r * 128 + c4] = vv;
        }
        __syncthreads();

        float accS[4][4];
#pragma unroll
        for (int i = 0; i < 4; i++)
#pragma unroll
            for (int j = 0; j < 4; j++) accS[i][j] = 0.f;
#pragma unroll 8
        for (int d = 0; d < 128; d++) {
            float4 a = *(const float4*)&Qt[d * QT_PITCH + ty * 4];
            float4 bb = *(const float4*)&Kt[d * QT_PITCH + tx * 4];
            float av[4] = {a.x, a.y, a.z, a.w};
            float bv[4] = {bb.x, bb.y, bb.z, bb.w};
#pragma unroll
            for (int i = 0; i < 4; i++)
#pragma unroll
                for (int j = 0; j < 4; j++) accS[i][j] += av[i] * bv[j];
        }

        bool diag = (kt == qt);
#pragma unroll
        for (int i = 0; i < 4; i++) {
#pragma unroll
            for (int j = 0; j < 4; j++) {
                float s = accS[i][j] * scale;
                if (diag && (tx * 4 + j > ty * 4 + i)) s = -1e30f;
                accS[i][j] = s;
            }
            float rm = fmaxf(fmaxf(accS[i][0], accS[i][1]), fmaxf(accS[i][2], accS[i][3]));
#pragma unroll
            for (int off = 8; off; off >>= 1) rm = fmaxf(rm, __shfl_xor_sync(0xffffffffu, rm, off));
            float mn = fmaxf(m[i], rm);
            float corr = __expf(m[i] - mn);
            float p[4], rs = 0.f;
#pragma unroll
            for (int j = 0; j < 4; j++) { p[j] = __expf(accS[i][j] - mn); rs += p[j]; }
#pragma unroll
            for (int off = 8; off; off >>= 1) rs += __shfl_xor_sync(0xffffffffu, rs, off);
            l[i] = l[i] * corr + rs;
            m[i] = mn;
#pragma unroll
            for (int c = 0; c < 8; c++) accO[i][c] *= corr;
#pragma unroll
            for (int j = 0; j < 4; j++) Pt[(tx * 4 + j) * QT_PITCH + ty * 4 + i] = p[j];
        }
        __syncthreads();

#pragma unroll 4
        for (int j = 0; j < 64; j++) {
            float4 p4 = *(const float4*)&Pt[j * QT_PITCH + ty * 4];
            float4 v0 = *(const float4*)&Vs[j * 128 + tx * 8];
            float4 v1 = *(const float4*)&Vs[j * 128 + tx * 8 + 4];
            float pp[4] = {p4.x, p4.y, p4.z, p4.w};
            float vv[8] = {v0.x, v0.y, v0.z, v0.w, v1.x, v1.y, v1.z, v1.w};
#pragma unroll
            for (int i = 0; i < 4; i++)
#pragma unroll
                for (int c = 0; c < 8; c++) accO[i][c] += pp[i] * vv[c];
        }
    }

#pragma unroll
    for (int i = 0; i < 4; i++) {
        float invl = 1.0f / l[i];
        int row = qbase + ty * 4 + i;
        size_t off = ((size_t)(b * SS + row) * NHQ + h) * HD + tx * 8;
        __nv_bfloat162* oph = (__nv_bfloat162*)(oh + off);
        __nv_bfloat162* opl = (__nv_bfloat162*)(ol + off);
#pragma unroll
        for (int c = 0; c < 8; c += 2) {
            __nv_bfloat162 hh, ll;
            split_store2(accO[i][c] * invl, accO[i][c+1] * invl, &hh, &ll);
            oph[c >> 1] = hh;
            opl[c >> 1] = ll;
        }
    }
}

// ======================= launch =======================
extern "C" void kernel_launch(void* const* d_in, const int* in_sizes, int n_in,
                              void* d_out, int out_size)
{
    const int*   positions = (const int*)  d_in[0];
    const float* hidden    = (const float*)d_in[1];
    const float* residual  = (const float*)d_in[2];
    const float* ln1       = (const float*)d_in[3];
    const float* ln2       = (const float*)d_in[4];
    const float* wq        = (const float*)d_in[5];
    const float* bq        = (const float*)d_in[6];
    const float* wk        = (const float*)d_in[7];
    const float* bk        = (const float*)d_in[8];
    const float* wv        = (const float*)d_in[9];
    const float* bv        = (const float*)d_in[10];
    const float* wo        = (const float*)d_in[11];
    const float* wgu       = (const float*)d_in[12];
    const float* wd        = (const float*)d_in[13];

    float* out_h   = (float*)d_out;
    float* out_res = out_h + (size_t)out_size / 2;

    float *res1, *qkv, *hattn;
    __nv_bfloat16 *xn_h, *xn_l, *at_h, *at_l, *h2_h, *h2_l, *ac_h, *ac_l;
    __nv_bfloat16 *qkvT_h, *qkvT_l, *woT_h, *woT_l, *guT_h, *guT_l, *wdT_h, *wdT_l;
    cudaGetSymbolAddress((void**)&res1,  g_res1);
    cudaGetSymbolAddress((void**)&qkv,   g_qkv);
    cudaGetSymbolAddress((void**)&hattn, g_hattn);
    cudaGetSymbolAddress((void**)&xn_h,  g_xn_h);
    cudaGetSymbolAddress((void**)&xn_l,  g_xn_l);
    cudaGetSymbolAddress((void**)&at_h,  g_at_h);
    cudaGetSymbolAddress((void**)&at_l,  g_at_l);
    cudaGetSymbolAddress((void**)&h2_h,  g_h2_h);
    cudaGetSymbolAddress((void**)&h2_l,  g_h2_l);
    cudaGetSymbolAddress((void**)&ac_h,  g_ac_h);
    cudaGetSymbolAddress((void**)&ac_l,  g_ac_l);
    cudaGetSymbolAddress((void**)&qkvT_h, g_qkvT_h);
    cudaGetSymbolAddress((void**)&qkvT_l, g_qkvT_l);
    cudaGetSymbolAddress((void**)&woT_h, g_woT_h);
    cudaGetSymbolAddress((void**)&woT_l, g_woT_l);
    cudaGetSymbolAddress((void**)&guT_h, g_guT_h);
    cudaGetSymbolAddress((void**)&guT_l, g_guT_l);
    cudaGetSymbolAddress((void**)&wdT_h, g_wdT_h);
    cudaGetSymbolAddress((void**)&wdT_l, g_wdT_l);

    cudaFuncSetAttribute(gemm_mma<0>, cudaFuncAttributeMaxDynamicSharedMemorySize, GEMM_SMEM);
    cudaFuncSetAttribute(gemm_mma<1>, cudaFuncAttributeMaxDynamicSharedMemorySize, GEMM_SMEM);
    cudaFuncSetAttribute(gemm_mma<2>, cudaFuncAttributeMaxDynamicSharedMemorySize, GEMM_SMEM);
    cudaFuncSetAttribute(flash_kernel, cudaFuncAttributeMaxDynamicSharedMemorySize, FLASH_SMEM);

    // 0. weight preprocessing
    wsplit_qkv_kernel<<<dim3(128, 64), dim3(32,8)>>>(wq, wk, wv, qkvT_h, qkvT_l);
    wsplit_kernel<<<dim3(64, 64), dim3(32,8)>>>(wo, woT_h, woT_l, NHQ*HD, HH);
    wsplit_gu_kernel<<<dim3(512, 64), dim3(32,8)>>>(wgu, guT_h, guT_l);
    wsplit_kernel<<<dim3(64, 256), dim3(32,8)>>>(wd, wdT_h, wdT_l, INTER, HH);

    // 1. res1 + rmsnorm
    add_rmsnorm_kernel<<<TT, 256>>>(hidden, residual, ln1, res1, xn_h, xn_l);

    // 2. fused QKV projection (N=4096)
    gemm_mma<1><<<dim3(32, 32), 256, GEMM_SMEM>>>(xn_h, xn_l, qkvT_h, qkvT_l,
        bq, bk, bv, qkv, nullptr, nullptr, TT, 4096, HH);

    // 3. RoPE in place
    rope_kernel<<<(TT * 24 * 64) / 256, 256>>>(qkv, positions);

    // 4. flash attention
    flash_kernel<<<dim3(SS / 64, NHQ, BB), 256, FLASH_SMEM>>>(qkv, at_h, at_l);

    // 5. output projection
    gemm_mma<0><<<dim3(16, 32), 256, GEMM_SMEM>>>(at_h, at_l, woT_h, woT_l,
        nullptr, nullptr, nullptr, hattn, nullptr, nullptr, TT, HH, NHQ*HD);

    // 6. res2 + rmsnorm
    add_rmsnorm_kernel<<<TT, 256>>>(hattn, res1, ln2, out_res, h2_h, h2_l);

    // 7. gate_up GEMM with fused SwiGLU -> bf16 split act
    gemm_mma<2><<<dim3(128, 32), 256, GEMM_SMEM>>>(h2_h, h2_l, guT_h, guT_l,
        nullptr, nullptr, nullptr, nullptr, ac_h, ac_l, TT, 16384, HH);

    // 8. down GEMM -> out first half
    gemm_mma<0><<<dim3(16, 32), 256, GEMM_SMEM>>>(ac_h, ac_l, wdT_h, wdT_l,
        nullptr, nullptr, nullptr, out_h, nullptr, nullptr, TT, HH, INTER);
}